// round 15
// baseline (speedup 1.0000x reference)
#include <cuda_runtime.h>
#include <cuda_bf16.h>

#define K_FEAT 4096
#define N_CTRL 256
#define M_INT  254       // interior knots
#define HALF   6         // tap half-width; truncation ~rho^7 (rel_err 3.3e-5 measured)
#define SEG    2         // segments per block
#define WINR   17        // shared value-row window: rows [s0-7, s0+9]

// Tap weight of the truncated closed-form inverse of the uniform [1 4 1]
// system: w(g,j) = ACP*(rho^|j-p| - rho^(j+p+2) - rho^(2m-j-p)), p=g-1,
// rho=-(2-sqrt(3)), ACP=(1/(2*sqrt(3)))*6/h^2. Powers via exp2f (MUFU).
__device__ __forceinline__ float tapw(int g, int j) {
    const int p = g - 1;
    const int d = j - p;
    if (g < 1 || g > M_INT || j < 0 || j >= M_INT || d > HALF || d < -HALF) return 0.0f;
    const float L   = -1.8999686269529529f;                       // log2(2-sqrt(3))
    const float ACP = 0.28867513459481288f * 6.0f * 255.0f * 255.0f;
    int e0 = d < 0 ? -d : d;
    int e1 = j + p + 2;
    int e2 = 2 * M_INT - j - p;
    float t0 = exp2f(L * (float)e0); if (e0 & 1) t0 = -t0;
    float t1 = exp2f(L * (float)e1); if (e1 & 1) t1 = -t1;
    float t2 = exp2f(L * (float)e2); if (e2 & 1) t2 = -t2;
    return ACP * (t0 - t1 - t2);
}

__device__ __forceinline__ float4 load_row_clamped(const float* __restrict__ values,
                                                   int row, int k) {
    int r = row < 0 ? 0 : (row > N_CTRL - 1 ? N_CTRL - 1 : row);
    return *reinterpret_cast<const float4*>(values + (size_t)r * K_FEAT + k);
}

// ---------------------------------------------------------------------------
// Single fused kernel, SINGLE WAVE. Each block owns 2 segments (s0, s0+1) x a
// 1024-col strip: the 3 needed gamma rows are computed with folded weights
// gamma_g = sum_r c_g(r)*v[r], c(r) = w(r)-2w(r-1)+w(r-2), over ONE shared
// 17-row window (17 loads, 204 FMA). Grid (4,128)=512 blocks; launch_bounds
// (256,5) keeps >=5 blocks/SM resident -> all 512 blocks in one wave, so the
// prologue's load-latency head is paid once in parallel instead of per-wave.
// Then 64 output rows stream per block with evict-first stores.
// ---------------------------------------------------------------------------
__global__ void __launch_bounds__(256, 5) spline_fused_kernel(
    const float* __restrict__ values, float* __restrict__ out, int ne1) {

    __shared__ float C[3][WINR];

    const int tid = threadIdx.x;
    const int s0  = blockIdx.y * SEG;         // first segment, 0..254
    const int rlo = s0 - 7;                   // first value row of window

    if (tid < 3 * WINR) {                     // 51 coefficient slots
        const int gi = tid / WINR;            // 0..2 -> gamma rows s0+gi
        const int u  = tid - gi * WINR;
        const int r  = rlo + u;
        C[gi][u] = tapw(s0 + gi, r) - 2.0f * tapw(s0 + gi, r - 1)
                   + tapw(s0 + gi, r - 2);
    }
    __syncthreads();

    const int k = (blockIdx.x * 256 + tid) * 4;

    float4 q[3];
    q[0] = make_float4(0.f, 0.f, 0.f, 0.f);
    q[1] = make_float4(0.f, 0.f, 0.f, 0.f);
    q[2] = make_float4(0.f, 0.f, 0.f, 0.f);
    float4 y0, y1, y2;

    #pragma unroll
    for (int u = 0; u < WINR; u++) {
        float4 v = load_row_clamped(values, rlo + u, k);   // unconditional
        if (u == 7) y0 = v;                                // row s0
        if (u == 8) y1 = v;                                // row s0+1
        if (u == 9) y2 = v;                                // row s0+2
        #pragma unroll
        for (int gi = 0; gi < 3; gi++) {
            const float c = C[gi][u];
            q[gi].x = fmaf(c, v.x, q[gi].x);
            q[gi].y = fmaf(c, v.y, q[gi].y);
            q[gi].z = fmaf(c, v.z, q[gi].z);
            q[gi].w = fmaf(c, v.w, q[gi].w);
        }
    }

    // --- evaluate & stream both segments ---
    const float inv_ne1 = 1.0f / (float)ne1;
    const float w = 1.0f / (6.0f * 255.0f * 255.0f);       // h^2/6

    #pragma unroll
    for (int seg = 0; seg < SEG; seg++) {
        const int s = s0 + seg;
        if (s > 254) break;
        const float4 ya = seg ? y1 : y0;
        const float4 yb = seg ? y2 : y1;
        const float4 qa = q[seg];
        const float4 qb = q[seg + 1];

        const int jstart = (s * ne1 + 254) / 255;          // ceil(s*ne1/255)
        const int jend   = (s < 254) ? ((s + 1) * ne1 + 254) / 255 - 1 : ne1;
        const int base   = s * ne1;

        #pragma unroll 4
        for (int j = jstart; j <= jend; j++) {
            float b  = (float)(j * 255 - base) * inv_ne1;  // in [0,1]
            float a  = 1.0f - b;
            float wa = (a * a * a - a) * w;
            float wb = (b * b * b - b) * w;
            float4 o;
            o.x = fmaf(a, ya.x, fmaf(b, yb.x, fmaf(wa, qa.x, wb * qb.x)));
            o.y = fmaf(a, ya.y, fmaf(b, yb.y, fmaf(wa, qa.y, wb * qb.y)));
            o.z = fmaf(a, ya.z, fmaf(b, yb.z, fmaf(wa, qa.z, wb * qb.z)));
            o.w = fmaf(a, ya.w, fmaf(b, yb.w, fmaf(wa, qa.w, wb * qb.w)));
            __stcs(reinterpret_cast<float4*>(out + (size_t)j * K_FEAT + k), o);
        }
    }
}

extern "C" void kernel_launch(void* const* d_in, const int* in_sizes, int n_in,
                              void* d_out, int out_size) {
    const float* values = (const float*)d_in[0];
    float* out = (float*)d_out;

    const int n_eval = out_size / K_FEAT;
    const int ne1 = n_eval - 1;

    dim3 grid(K_FEAT / (256 * 4), (N_CTRL - 1 + SEG - 1) / SEG);   // (4, 128)
    spline_fused_kernel<<<grid, 256>>>(values, out, ne1);
}

// round 17
// speedup vs baseline: 1.0052x; 1.0052x over previous
#include <cuda_runtime.h>
#include <cuda_bf16.h>

#define K_FEAT 4096
#define N_CTRL 256
#define M_INT  254       // interior knots
#define HALF   6         // tap half-width; truncation ~rho^7 (rel_err 3.3e-5 measured)
#define SEG    2         // segments per block
#define WINR   17        // shared value-row window: rows [s0-7, s0+9]

// Tap weight of the truncated closed-form inverse of the uniform [1 4 1]
// system: w(g,j) = ACP*(rho^|j-p| - rho^(j+p+2) - rho^(2m-j-p)), p=g-1,
// rho=-(2-sqrt(3)), ACP=(1/(2*sqrt(3)))*6/h^2. Powers via exp2f (MUFU).
__device__ __forceinline__ float tapw(int g, int j) {
    const int p = g - 1;
    const int d = j - p;
    if (g < 1 || g > M_INT || j < 0 || j >= M_INT || d > HALF || d < -HALF) return 0.0f;
    const float L   = -1.8999686269529529f;                       // log2(2-sqrt(3))
    const float ACP = 0.28867513459481288f * 6.0f * 255.0f * 255.0f;
    int e0 = d < 0 ? -d : d;
    int e1 = j + p + 2;
    int e2 = 2 * M_INT - j - p;
    float t0 = exp2f(L * (float)e0); if (e0 & 1) t0 = -t0;
    float t1 = exp2f(L * (float)e1); if (e1 & 1) t1 = -t1;
    float t2 = exp2f(L * (float)e2); if (e2 & 1) t2 = -t2;
    return ACP * (t0 - t1 - t2);
}

__device__ __forceinline__ float4 load_row_clamped(const float* __restrict__ values,
                                                   int row, int k) {
    int r = row < 0 ? 0 : (row > N_CTRL - 1 ? N_CTRL - 1 : row);
    return *reinterpret_cast<const float4*>(values + (size_t)r * K_FEAT + k);
}

// ---------------------------------------------------------------------------
// Single fused kernel. Each block owns 2 segments (s0, s0+1) x a 1024-col
// strip: 3 gamma rows via folded weights gamma_g = sum_r c_g(r)*v[r],
// c(r) = w(r)-2w(r-1)+w(r-2), over ONE shared 17-row window (17 loads,
// 204 FMA). Occupancy is the binding constraint for the store stream, so
// launch_bounds(256,6) caps regs at 42 (6 blocks/SM, ~75% occ); to fit, the
// y rows are NOT captured in the conv loop (saves 12 live regs) but reloaded
// afterwards from L1. 512 blocks = single wave. 64 output rows stream per
// block with evict-first stores.
// ---------------------------------------------------------------------------
__global__ void __launch_bounds__(256, 6) spline_fused_kernel(
    const float* __restrict__ values, float* __restrict__ out, int ne1) {

    __shared__ float C[3][WINR];

    const int tid = threadIdx.x;
    const int s0  = blockIdx.y * SEG;         // first segment, 0..254
    const int rlo = s0 - 7;                   // first value row of window

    if (tid < 3 * WINR) {                     // 51 coefficient slots
        const int gi = tid / WINR;            // 0..2 -> gamma rows s0+gi
        const int u  = tid - gi * WINR;
        const int r  = rlo + u;
        C[gi][u] = tapw(s0 + gi, r) - 2.0f * tapw(s0 + gi, r - 1)
                   + tapw(s0 + gi, r - 2);
    }
    __syncthreads();

    const int k = (blockIdx.x * 256 + tid) * 4;

    float4 q0 = make_float4(0.f, 0.f, 0.f, 0.f);
    float4 q1 = make_float4(0.f, 0.f, 0.f, 0.f);
    float4 q2 = make_float4(0.f, 0.f, 0.f, 0.f);

    #pragma unroll
    for (int u = 0; u < WINR; u++) {
        float4 v = load_row_clamped(values, rlo + u, k);   // unconditional
        float c0 = C[0][u], c1 = C[1][u], c2 = C[2][u];
        q0.x = fmaf(c0, v.x, q0.x); q0.y = fmaf(c0, v.y, q0.y);
        q0.z = fmaf(c0, v.z, q0.z); q0.w = fmaf(c0, v.w, q0.w);
        q1.x = fmaf(c1, v.x, q1.x); q1.y = fmaf(c1, v.y, q1.y);
        q1.z = fmaf(c1, v.z, q1.z); q1.w = fmaf(c1, v.w, q1.w);
        q2.x = fmaf(c2, v.x, q2.x); q2.y = fmaf(c2, v.y, q2.y);
        q2.z = fmaf(c2, v.z, q2.z); q2.w = fmaf(c2, v.w, q2.w);
    }

    // y rows were part of the window above -> L1 hits, cheap reload.
    const float4 y0 = load_row_clamped(values, s0,     k);
    const float4 y1 = load_row_clamped(values, s0 + 1, k);
    const float4 y2 = load_row_clamped(values, s0 + 2, k);

    // --- evaluate & stream both segments ---
    const float inv_ne1 = 1.0f / (float)ne1;
    const float w = 1.0f / (6.0f * 255.0f * 255.0f);       // h^2/6

    #pragma unroll
    for (int seg = 0; seg < SEG; seg++) {
        const int s = s0 + seg;
        if (s > 254) break;
        const float4 ya = seg ? y1 : y0;
        const float4 yb = seg ? y2 : y1;
        const float4 qa = seg ? q1 : q0;
        const float4 qb = seg ? q2 : q1;

        const int jstart = (s * ne1 + 254) / 255;          // ceil(s*ne1/255)
        const int jend   = (s < 254) ? ((s + 1) * ne1 + 254) / 255 - 1 : ne1;
        const int base   = s * ne1;

        #pragma unroll 4
        for (int j = jstart; j <= jend; j++) {
            float b  = (float)(j * 255 - base) * inv_ne1;  // in [0,1]
            float a  = 1.0f - b;
            float wa = (a * a * a - a) * w;
            float wb = (b * b * b - b) * w;
            float4 o;
            o.x = fmaf(a, ya.x, fmaf(b, yb.x, fmaf(wa, qa.x, wb * qb.x)));
            o.y = fmaf(a, ya.y, fmaf(b, yb.y, fmaf(wa, qa.y, wb * qb.y)));
            o.z = fmaf(a, ya.z, fmaf(b, yb.z, fmaf(wa, qa.z, wb * qb.z)));
            o.w = fmaf(a, ya.w, fmaf(b, yb.w, fmaf(wa, qa.w, wb * qb.w)));
            __stcs(reinterpret_cast<float4*>(out + (size_t)j * K_FEAT + k), o);
        }
    }
}

extern "C" void kernel_launch(void* const* d_in, const int* in_sizes, int n_in,
                              void* d_out, int out_size) {
    const float* values = (const float*)d_in[0];
    float* out = (float*)d_out;

    const int n_eval = out_size / K_FEAT;
    const int ne1 = n_eval - 1;

    dim3 grid(K_FEAT / (256 * 4), (N_CTRL - 1 + SEG - 1) / SEG);   // (4, 128)
    spline_fused_kernel<<<grid, 256>>>(values, out, ne1);
}